// round 1
// baseline (speedup 1.0000x reference)
#include <cuda_runtime.h>

#define NB 16
#define NC 512
#define NN 1024
#define NH 8
#define ND 64

// Scratch (device globals: allocation-free per harness rules)
__device__ float g_q[(size_t)NB * NC * NN];
__device__ float g_k[(size_t)NB * NC * NN];
__device__ float g_v[(size_t)NB * NC * NN];
__device__ float g_pos[(size_t)NC * NN];   // [head*d][N]

// pos[h,d,n] = rel_h[h,d,hc] + rel_w[h,d,w],  n = w*32 + hc
__global__ void pos_kernel(const float* __restrict__ rel_h,
                           const float* __restrict__ rel_w) {
    int idx = blockIdx.x * blockDim.x + threadIdx.x;
    if (idx >= NC * NN) return;
    int hd = idx / NN, n = idx % NN;
    int w = n >> 5, hc = n & 31;
    g_pos[idx] = rel_h[hd * 32 + hc] + rel_w[hd * 32 + w];
}

// out[b][o][n] = sum_c W[o][c] x[b][c][n] + bias[o]
// grid: (N/64, C/64, B*3), 256 threads, 4x4 per thread
__global__ __launch_bounds__(256) void qkv_kernel(
    const float* __restrict__ x,
    const float* __restrict__ Wq, const float* __restrict__ bq,
    const float* __restrict__ Wk, const float* __restrict__ bk,
    const float* __restrict__ Wv, const float* __restrict__ bv)
{
    __shared__ float Ws[16][68];  // [c][o] (transposed tile)
    __shared__ float Xs[16][68];  // [c][n]

    int which = blockIdx.z % 3;
    int b     = blockIdx.z / 3;
    const float* Wm   = (which == 0) ? Wq : (which == 1) ? Wk : Wv;
    const float* bias = (which == 0) ? bq : (which == 1) ? bk : bv;
    float*       out  = (which == 0) ? g_q : (which == 1) ? g_k : g_v;

    int oT = blockIdx.y * 64;
    int nT = blockIdx.x * 64;
    int tid = threadIdx.x;
    int ty = tid >> 4, tx = tid & 15;

    const float* xb = x + (size_t)b * NC * NN;
    float acc[4][4] = {};

    int wr = tid >> 2;            // 0..63 (o within tile)
    int wc = (tid & 3) * 4;       // 0..12 (c within tile)
    int xr = tid >> 4;            // 0..15 (c within tile)
    int xc = (tid & 15) * 4;      // 0..60 (n within tile)

    for (int ct = 0; ct < NC; ct += 16) {
        float4 wv = *(const float4*)&Wm[(size_t)(oT + wr) * NC + ct + wc];
        Ws[wc + 0][wr] = wv.x;
        Ws[wc + 1][wr] = wv.y;
        Ws[wc + 2][wr] = wv.z;
        Ws[wc + 3][wr] = wv.w;
        *(float4*)&Xs[xr][xc] = *(const float4*)&xb[(size_t)(ct + xr) * NN + nT + xc];
        __syncthreads();
        #pragma unroll
        for (int kk = 0; kk < 16; kk++) {
            float4 a = *(float4*)&Ws[kk][ty * 4];
            float4 v4 = *(float4*)&Xs[kk][tx * 4];
            acc[0][0] += a.x * v4.x; acc[0][1] += a.x * v4.y; acc[0][2] += a.x * v4.z; acc[0][3] += a.x * v4.w;
            acc[1][0] += a.y * v4.x; acc[1][1] += a.y * v4.y; acc[1][2] += a.y * v4.z; acc[1][3] += a.y * v4.w;
            acc[2][0] += a.z * v4.x; acc[2][1] += a.z * v4.y; acc[2][2] += a.z * v4.z; acc[2][3] += a.z * v4.w;
            acc[3][0] += a.w * v4.x; acc[3][1] += a.w * v4.y; acc[3][2] += a.w * v4.z; acc[3][3] += a.w * v4.w;
        }
        __syncthreads();
    }
    #pragma unroll
    for (int u = 0; u < 4; u++) {
        float bi = bias[oT + ty * 4 + u];
        float4 r;
        r.x = acc[u][0] + bi; r.y = acc[u][1] + bi; r.z = acc[u][2] + bi; r.w = acc[u][3] + bi;
        *(float4*)&out[((size_t)b * NC + oT + ty * 4 + u) * NN + nT + tx * 4] = r;
    }
}

// Flash-style attention per (b, h, query-tile of 64).
// Q'[128,i] = [q ; pos], K'[128,j] = [k ; q], V[64,j].
// No online max (scores bounded ~|32|): P = exp(S), O += P*V^T, normalize at end.
__global__ __launch_bounds__(256) void attn_kernel(const float* __restrict__ x,
                                                   float* __restrict__ out)
{
    extern __shared__ float sm[];
    float* Qs = sm;                 // [128][68]
    float* KP = sm + 128 * 68;      // [128][68] K' tile; reused as P [64 j][68 i]
    float* Vs = sm + 2 * 128 * 68;  // [64 j][68 dd]

    int b = blockIdx.z, h = blockIdx.y;
    int i0 = blockIdx.x * 64;
    int tid = threadIdx.x;
    int ty = tid >> 4, tx = tid & 15;

    const float* qb = g_q + ((size_t)b * NC + h * ND) * NN;
    const float* kb = g_k + ((size_t)b * NC + h * ND) * NN;
    const float* vb = g_v + ((size_t)b * NC + h * ND) * NN;
    const float* pb = g_pos + (size_t)h * ND * NN;

    // Load Q' tile [128][64]
    for (int idx = tid; idx < 128 * 64; idx += 256) {
        int r = idx >> 6, cL = idx & 63;
        float val = (r < 64) ? qb[r * NN + i0 + cL] : pb[(r - 64) * NN + i0 + cL];
        Qs[r * 68 + cL] = val;
    }

    float accO[4][4] = {};
    float rowsum[4] = {};

    for (int jt = 0; jt < 16; jt++) {
        int j0 = jt * 64;
        for (int idx = tid; idx < 128 * 64; idx += 256) {
            int r = idx >> 6, cL = idx & 63;
            float val = (r < 64) ? kb[r * NN + j0 + cL] : qb[(r - 64) * NN + j0 + cL];
            KP[r * 68 + cL] = val;
        }
        for (int idx = tid; idx < 64 * 64; idx += 256) {
            int dd = idx >> 6, j = idx & 63;
            Vs[j * 68 + dd] = vb[dd * NN + j0 + j];
        }
        __syncthreads();

        // S[4][4] = Q'^T K' over 128 dims
        float S[4][4] = {};
        #pragma unroll 8
        for (int kk = 0; kk < 128; kk++) {
            float4 qv = *(float4*)&Qs[kk * 68 + ty * 4];
            float4 kv = *(float4*)&KP[kk * 68 + tx * 4];
            S[0][0] += qv.x * kv.x; S[0][1] += qv.x * kv.y; S[0][2] += qv.x * kv.z; S[0][3] += qv.x * kv.w;
            S[1][0] += qv.y * kv.x; S[1][1] += qv.y * kv.y; S[1][2] += qv.y * kv.z; S[1][3] += qv.y * kv.w;
            S[2][0] += qv.z * kv.x; S[2][1] += qv.z * kv.y; S[2][2] += qv.z * kv.z; S[2][3] += qv.z * kv.w;
            S[3][0] += qv.w * kv.x; S[3][1] += qv.w * kv.y; S[3][2] += qv.w * kv.z; S[3][3] += qv.w * kv.w;
        }
        __syncthreads();  // everyone done reading KP before P overwrites it

        float rs[4];
        #pragma unroll
        for (int u = 0; u < 4; u++) {
            #pragma unroll
            for (int v = 0; v < 4; v++) S[u][v] = __expf(S[u][v]);
            rs[u] = S[u][0] + S[u][1] + S[u][2] + S[u][3];
        }
        // P -> KP as [j][i]
        #pragma unroll
        for (int v = 0; v < 4; v++)
            #pragma unroll
            for (int u = 0; u < 4; u++)
                KP[(tx * 4 + v) * 68 + ty * 4 + u] = S[u][v];
        // reduce row sums across the 16 tx lanes
        #pragma unroll
        for (int off = 1; off < 16; off <<= 1)
            #pragma unroll
            for (int u = 0; u < 4; u++)
                rs[u] += __shfl_xor_sync(0xffffffffu, rs[u], off, 16);
        #pragma unroll
        for (int u = 0; u < 4; u++) rowsum[u] += rs[u];
        __syncthreads();  // P visible

        // O[i][dd] += sum_j P[j][i] * V[j][dd]
        #pragma unroll 8
        for (int j = 0; j < 64; j++) {
            float4 vv = *(float4*)&Vs[j * 68 + tx * 4];
            float p0 = KP[j * 68 + ty * 4 + 0];
            float p1 = KP[j * 68 + ty * 4 + 1];
            float p2 = KP[j * 68 + ty * 4 + 2];
            float p3 = KP[j * 68 + ty * 4 + 3];
            accO[0][0] += p0 * vv.x; accO[0][1] += p0 * vv.y; accO[0][2] += p0 * vv.z; accO[0][3] += p0 * vv.w;
            accO[1][0] += p1 * vv.x; accO[1][1] += p1 * vv.y; accO[1][2] += p1 * vv.z; accO[1][3] += p1 * vv.w;
            accO[2][0] += p2 * vv.x; accO[2][1] += p2 * vv.y; accO[2][2] += p2 * vv.z; accO[2][3] += p2 * vv.w;
            accO[3][0] += p3 * vv.x; accO[3][1] += p3 * vv.y; accO[3][2] += p3 * vv.z; accO[3][3] += p3 * vv.w;
        }
        __syncthreads();  // done with KP/Vs before next tile load
    }

    // Normalize and write (via smem transpose to get coalesced [c][n] writes)
    float inv[4];
    #pragma unroll
    for (int u = 0; u < 4; u++) inv[u] = 1.0f / rowsum[u];
    #pragma unroll
    for (int v = 0; v < 4; v++)
        #pragma unroll
        for (int u = 0; u < 4; u++)
            Qs[(tx * 4 + v) * 68 + ty * 4 + u] = accO[u][v] * inv[u];  // Os[dd][i]
    __syncthreads();

    const float* xb = x + ((size_t)b * NC + h * ND) * NN;
    float*       ob = out + ((size_t)b * NC + h * ND) * NN;
    for (int idx = tid; idx < 64 * 64; idx += 256) {
        int dd = idx >> 6, iL = idx & 63;
        ob[dd * NN + i0 + iL] = Qs[dd * 68 + iL] + xb[dd * NN + i0 + iL];
    }
}

extern "C" void kernel_launch(void* const* d_in, const int* in_sizes, int n_in,
                              void* d_out, int out_size) {
    (void)in_sizes; (void)n_in; (void)out_size;
    const float* x     = (const float*)d_in[0];
    const float* Wq    = (const float*)d_in[1];
    const float* bq    = (const float*)d_in[2];
    const float* Wk    = (const float*)d_in[3];
    const float* bk    = (const float*)d_in[4];
    const float* Wv    = (const float*)d_in[5];
    const float* bv    = (const float*)d_in[6];
    const float* rel_h = (const float*)d_in[7];
    const float* rel_w = (const float*)d_in[8];
    // d_in[9] (reg_qk) and d_in[10] (reg_v) are provably dead: the reg group is
    // sliced away by out[:, :head] and softmax/PV are group-independent.
    float* out = (float*)d_out;

    cudaFuncSetAttribute(attn_kernel, cudaFuncAttributeMaxDynamicSharedMemorySize,
                         320 * 68 * 4);

    pos_kernel<<<(NC * NN + 255) / 256, 256>>>(rel_h, rel_w);
    qkv_kernel<<<dim3(NN / 64, NC / 64, NB * 3), 256>>>(x, Wq, bq, Wk, bk, Wv, bv);
    attn_kernel<<<dim3(NN / 64, NH, NB), 256, 320 * 68 * 4>>>(x, out);
}